// round 9
// baseline (speedup 1.0000x reference)
#include <cuda_runtime.h>
#include <cuda_fp16.h>

#define NN   50000
#define DD   128
#define NV2  (NN * DD / 4)      // uint2 (4 halves) per T slot = 1.6M
#define NNZ_CAP 800000
#define MCAP 32

// ---- static scratch (allocation-free rule: __device__ globals) ----
__device__ __half g_T[MCAP * NN * DD];   // all Chebyshev iterates, fp16 (slot k = T_k)
__device__ int   g_cnt[NN];
__device__ int   g_rptr[NN + 1];
__device__ int   g_cursor[NN];
__device__ int2  g_edges[NNZ_CAP];       // {col, val-as-int}

// ---------------- CSR build ----------------
__global__ void hist_kernel(const int* __restrict__ rows, int nnz) {
    int i = blockIdx.x * blockDim.x + threadIdx.x;
    if (i < nnz) atomicAdd(&g_cnt[rows[i]], 1);
}

__global__ void scan_kernel(int nnz) {
    __shared__ int sh[1024];
    const int t  = threadIdx.x;
    const int CH = (NN + 1023) / 1024;
    const int base = t * CH;

    int sum = 0;
    #pragma unroll 4
    for (int i = 0; i < CH; i++) {
        int idx = base + i;
        if (idx < NN) sum += g_cnt[idx];
    }
    sh[t] = sum;
    __syncthreads();

    for (int d = 1; d < 1024; d <<= 1) {
        int v = (t >= d) ? sh[t - d] : 0;
        __syncthreads();
        sh[t] += v;
        __syncthreads();
    }

    int off = sh[t] - sum;   // exclusive prefix for this chunk
    for (int i = 0; i < CH; i++) {
        int idx = base + i;
        if (idx < NN) {
            g_rptr[idx]   = off;
            g_cursor[idx] = off;
            off += g_cnt[idx];
        }
    }
    if (t == 1023) g_rptr[NN] = nnz;
}

__global__ void scatter_kernel(const int* __restrict__ rows,
                               const int* __restrict__ cols,
                               const float* __restrict__ vals, int nnz) {
    int i = blockIdx.x * blockDim.x + threadIdx.x;
    if (i < nnz) {
        int r = rows[i];
        int p = atomicAdd(&g_cursor[r], 1);
        g_edges[p] = make_int2(cols[i], __float_as_int(vals[i]));
    }
}

// ---------------- fp32 -> fp16 convert (X -> slot 0) ----------------
__global__ void convert_kernel(const float* __restrict__ X, __half* __restrict__ H) {
    int i = blockIdx.x * blockDim.x + threadIdx.x;          // 4 elems per thread
    if (i < NV2) {
        float4 v = __ldg(&((const float4*)X)[i]);
        __half2 lo = __floats2half2_rn(v.x, v.y);
        __half2 hi = __floats2half2_rn(v.z, v.w);
        uint2 r;
        r.x = *(unsigned int*)&lo;
        r.y = *(unsigned int*)&hi;
        ((uint2*)H)[i] = r;
    }
}

// ---------------- helpers ----------------
__device__ __forceinline__ void fma_h(float4& a, uint2 r, float v) {
    float2 lo = __half22float2(*(const __half2*)&r.x);
    float2 hi = __half22float2(*(const __half2*)&r.y);
    a.x += v * lo.x; a.y += v * lo.y; a.z += v * hi.x; a.w += v * hi.y;
}

__device__ __forceinline__ uint2 pack_h(float4 t) {
    __half2 lo = __floats2half2_rn(t.x, t.y);
    __half2 hi = __floats2half2_rn(t.z, t.w);
    uint2 r;
    r.x = *(unsigned int*)&lo;
    r.y = *(unsigned int*)&hi;
    return r;
}

// SpMM for one row; broadcast edge loads (all lanes same addr = 1 line),
// unroll-by-8 to keep 8 edge loads + 8 gathers outstanding.
__device__ __forceinline__ float4 spmm_row_h(const __half* __restrict__ T,
                                             int s, int e, int lane) {
    float4 a = make_float4(0.f, 0.f, 0.f, 0.f);
    const uint2* Tv = (const uint2*)T;    // 4 halves per uint2; row stride = 32
    int i = s;
    for (; i + 7 < e; i += 8) {
        int2 e0 = __ldg(&g_edges[i]);
        int2 e1 = __ldg(&g_edges[i + 1]);
        int2 e2 = __ldg(&g_edges[i + 2]);
        int2 e3 = __ldg(&g_edges[i + 3]);
        int2 e4 = __ldg(&g_edges[i + 4]);
        int2 e5 = __ldg(&g_edges[i + 5]);
        int2 e6 = __ldg(&g_edges[i + 6]);
        int2 e7 = __ldg(&g_edges[i + 7]);
        uint2 r0 = __ldg(&Tv[e0.x * 32 + lane]);
        uint2 r1 = __ldg(&Tv[e1.x * 32 + lane]);
        uint2 r2 = __ldg(&Tv[e2.x * 32 + lane]);
        uint2 r3 = __ldg(&Tv[e3.x * 32 + lane]);
        uint2 r4 = __ldg(&Tv[e4.x * 32 + lane]);
        uint2 r5 = __ldg(&Tv[e5.x * 32 + lane]);
        uint2 r6 = __ldg(&Tv[e6.x * 32 + lane]);
        uint2 r7 = __ldg(&Tv[e7.x * 32 + lane]);
        fma_h(a, r0, __int_as_float(e0.y));
        fma_h(a, r1, __int_as_float(e1.y));
        fma_h(a, r2, __int_as_float(e2.y));
        fma_h(a, r3, __int_as_float(e3.y));
        fma_h(a, r4, __int_as_float(e4.y));
        fma_h(a, r5, __int_as_float(e5.y));
        fma_h(a, r6, __int_as_float(e6.y));
        fma_h(a, r7, __int_as_float(e7.y));
    }
    for (; i + 3 < e; i += 4) {
        int2 e0 = __ldg(&g_edges[i]);
        int2 e1 = __ldg(&g_edges[i + 1]);
        int2 e2 = __ldg(&g_edges[i + 2]);
        int2 e3 = __ldg(&g_edges[i + 3]);
        uint2 r0 = __ldg(&Tv[e0.x * 32 + lane]);
        uint2 r1 = __ldg(&Tv[e1.x * 32 + lane]);
        uint2 r2 = __ldg(&Tv[e2.x * 32 + lane]);
        uint2 r3 = __ldg(&Tv[e3.x * 32 + lane]);
        fma_h(a, r0, __int_as_float(e0.y));
        fma_h(a, r1, __int_as_float(e1.y));
        fma_h(a, r2, __int_as_float(e2.y));
        fma_h(a, r3, __int_as_float(e3.y));
    }
    for (; i < e; i++) {
        int2 e0 = __ldg(&g_edges[i]);
        uint2 r0 = __ldg(&Tv[e0.x * 32 + lane]);
        fma_h(a, r0, __int_as_float(e0.y));
    }
    return a;
}

// T1 = L @ T0 (slot0 -> slot1); one row per warp
__global__ void cheb_first(const __half* __restrict__ T0,
                           __half* __restrict__ T1) {
    int gw   = (blockIdx.x * blockDim.x + threadIdx.x) >> 5;
    int lane = threadIdx.x & 31;
    if (gw >= NN) return;
    int s = g_rptr[gw], e = g_rptr[gw + 1];

    float4 a = spmm_row_h(T0, s, e, lane);
    ((uint2*)T1)[gw * 32 + lane] = pack_h(a);
}

// Tk = 2*(L @ Tc) - Tp  (slot k-1, slot k-2 -> slot k); one row per warp
__global__ void cheb_step(const __half* __restrict__ Tc,
                          const __half* __restrict__ Tp,
                          __half* __restrict__ Tn) {
    int gw   = (blockIdx.x * blockDim.x + threadIdx.x) >> 5;
    int lane = threadIdx.x & 31;
    if (gw >= NN) return;
    int s = g_rptr[gw], e = g_rptr[gw + 1];

    float4 a = spmm_row_h(Tc, s, e, lane);

    int idx = gw * 32 + lane;
    uint2 tpr = __ldg(&((const uint2*)Tp)[idx]);
    float2 tplo = __half22float2(*(const __half2*)&tpr.x);
    float2 tphi = __half22float2(*(const __half2*)&tpr.y);

    float4 tk;
    tk.x = 2.f * a.x - tplo.x;
    tk.y = 2.f * a.y - tplo.y;
    tk.z = 2.f * a.z - tphi.x;
    tk.w = 2.f * a.w - tphi.y;
    ((uint2*)Tn)[idx] = pack_h(tk);
}

// out = sum_k coeffs[k] * T_k   (single streaming pass over all slots)
__global__ void reduce_kernel(const __half* __restrict__ T,
                              const float* __restrict__ coeffs,
                              float* __restrict__ out, int M) {
    int i = blockIdx.x * blockDim.x + threadIdx.x;
    if (i >= NV2) return;
    const uint2* base = (const uint2*)T;
    float4 a = make_float4(0.f, 0.f, 0.f, 0.f);
    int k = 0;
    for (; k + 3 < M; k += 4) {
        uint2 r0 = __ldg(&base[(size_t)(k + 0) * NV2 + i]);
        uint2 r1 = __ldg(&base[(size_t)(k + 1) * NV2 + i]);
        uint2 r2 = __ldg(&base[(size_t)(k + 2) * NV2 + i]);
        uint2 r3 = __ldg(&base[(size_t)(k + 3) * NV2 + i]);
        fma_h(a, r0, __ldg(&coeffs[k + 0]));
        fma_h(a, r1, __ldg(&coeffs[k + 1]));
        fma_h(a, r2, __ldg(&coeffs[k + 2]));
        fma_h(a, r3, __ldg(&coeffs[k + 3]));
    }
    for (; k < M; k++) {
        uint2 r = __ldg(&base[(size_t)k * NV2 + i]);
        fma_h(a, r, __ldg(&coeffs[k]));
    }
    ((float4*)out)[i] = a;
}

// ---------------- launch ----------------
extern "C" void kernel_launch(void* const* d_in, const int* in_sizes, int n_in,
                              void* d_out, int out_size) {
    const int*   rows   = (const int*)d_in[0];
    const int*   cols   = (const int*)d_in[1];
    const float* vals   = (const float*)d_in[2];
    const float* X      = (const float*)d_in[3];
    const float* coeffs = (const float*)d_in[4];
    const int nnz = in_sizes[0];
    const int M   = in_sizes[4];

    void* p;
    __half* T;
    int* pcnt;
    cudaGetSymbolAddress(&p, g_T);   T = (__half*)p;
    cudaGetSymbolAddress(&p, g_cnt); pcnt = (int*)p;

    const size_t SLOT = (size_t)NN * DD;

    // ---- CSR build (in-graph, re-done every replay) ----
    cudaMemsetAsync(pcnt, 0, NN * sizeof(int));
    hist_kernel<<<(nnz + 255) / 256, 256>>>(rows, nnz);
    scan_kernel<<<1, 1024>>>(nnz);
    scatter_kernel<<<(nnz + 255) / 256, 256>>>(rows, cols, vals, nnz);

    // ---- X -> fp16 slot 0 ----
    convert_kernel<<<(NV2 + 255) / 256, 256>>>(X, T);

    // ---- Chebyshev recurrence: slot k = T_k (one row per warp) ----
    const int threads = 256;                 // 8 rows per block
    const int rowsPerBlk = threads / 32;
    const int grid = (NN + rowsPerBlk - 1) / rowsPerBlk;

    cheb_first<<<grid, threads>>>(T, T + SLOT);
    for (int k = 2; k < M; k++) {
        cheb_step<<<grid, threads>>>(T + (size_t)(k - 1) * SLOT,
                                     T + (size_t)(k - 2) * SLOT,
                                     T + (size_t)k * SLOT);
    }

    // ---- final weighted reduction ----
    reduce_kernel<<<(NV2 + 255) / 256, 256>>>(T, coeffs, (float*)d_out, M);
}

// round 10
// speedup vs baseline: 1.2136x; 1.2136x over previous
#include <cuda_runtime.h>
#include <cuda_fp16.h>

#define NN   50000
#define DD   128
#define NV2  (NN * DD / 4)      // uint2 (4 halves) per T slot = 1.6M
#define NNZ_CAP 800000
#define MCAP 32

#define SCAN_BLK 256
#define NBLK ((NN + SCAN_BLK - 1) / SCAN_BLK)   // 196

// ---- static scratch (allocation-free rule: __device__ globals) ----
__device__ __half g_T[MCAP * NN * DD];   // all Chebyshev iterates, fp16 (slot k = T_k)
__device__ int   g_cnt[NN];
__device__ int   g_rptr[NN + 1];
__device__ int   g_cursor[NN];
__device__ int   g_blksum[NBLK];
__device__ int   g_blkoff[NBLK];
__device__ int2  g_edges[NNZ_CAP];       // {col, val-as-int}

// ---------------- CSR build ----------------
__global__ void hist_kernel(const int* __restrict__ rows, int nnz) {
    int i = blockIdx.x * blockDim.x + threadIdx.x;
    if (i < nnz) atomicAdd(&g_cnt[rows[i]], 1);
}

// per-block exclusive scan of g_cnt -> g_rptr (local part), block total -> g_blksum
__global__ void scan_blocks_kernel() {
    __shared__ int sh[SCAN_BLK];
    const int b = blockIdx.x, t = threadIdx.x;
    const int i = b * SCAN_BLK + t;
    int v = (i < NN) ? g_cnt[i] : 0;
    sh[t] = v;
    __syncthreads();
    for (int d = 1; d < SCAN_BLK; d <<= 1) {
        int x = (t >= d) ? sh[t - d] : 0;
        __syncthreads();
        sh[t] += x;
        __syncthreads();
    }
    if (i < NN) g_rptr[i] = sh[t] - v;     // exclusive within block
    if (t == SCAN_BLK - 1) g_blksum[b] = sh[t];
}

// single block scans the 196 block totals
__global__ void scan_totals_kernel(int nnz) {
    __shared__ int sh[NBLK];
    const int t = threadIdx.x;
    int v = 0;
    if (t < NBLK) { v = g_blksum[t]; sh[t] = v; }
    __syncthreads();
    for (int d = 1; d < NBLK; d <<= 1) {
        int x = (t >= d && t < NBLK) ? sh[t - d] : 0;
        __syncthreads();
        if (t < NBLK) sh[t] += x;
        __syncthreads();
    }
    if (t < NBLK) g_blkoff[t] = sh[t] - v;  // exclusive
    if (t == 0) g_rptr[NN] = nnz;
}

// add block offsets, init cursors
__global__ void scan_fixup_kernel() {
    const int i = blockIdx.x * blockDim.x + threadIdx.x;
    if (i < NN) {
        int r = g_rptr[i] + g_blkoff[blockIdx.x];
        g_rptr[i]   = r;
        g_cursor[i] = r;
    }
}

__global__ void scatter_kernel(const int* __restrict__ rows,
                               const int* __restrict__ cols,
                               const float* __restrict__ vals, int nnz) {
    int i = blockIdx.x * blockDim.x + threadIdx.x;
    if (i < nnz) {
        int r = rows[i];
        int p = atomicAdd(&g_cursor[r], 1);
        g_edges[p] = make_int2(cols[i], __float_as_int(vals[i]));
    }
}

// ---------------- fp32 -> fp16 convert (X -> slot 0) ----------------
__global__ void convert_kernel(const float* __restrict__ X, __half* __restrict__ H) {
    int i = blockIdx.x * blockDim.x + threadIdx.x;          // 4 elems per thread
    if (i < NV2) {
        float4 v = __ldg(&((const float4*)X)[i]);
        __half2 lo = __floats2half2_rn(v.x, v.y);
        __half2 hi = __floats2half2_rn(v.z, v.w);
        uint2 r;
        r.x = *(unsigned int*)&lo;
        r.y = *(unsigned int*)&hi;
        ((uint2*)H)[i] = r;
    }
}

// ---------------- helpers ----------------
__device__ __forceinline__ void fma_h(float4& a, uint2 r, float v) {
    float2 lo = __half22float2(*(const __half2*)&r.x);
    float2 hi = __half22float2(*(const __half2*)&r.y);
    a.x += v * lo.x; a.y += v * lo.y; a.z += v * hi.x; a.w += v * hi.y;
}

__device__ __forceinline__ uint2 pack_h(float4 t) {
    __half2 lo = __floats2half2_rn(t.x, t.y);
    __half2 hi = __floats2half2_rn(t.z, t.w);
    uint2 r;
    r.x = *(unsigned int*)&lo;
    r.y = *(unsigned int*)&hi;
    return r;
}

// SpMM for one row (R6-proven form: unroll-by-4, broadcast edge loads)
__device__ __forceinline__ float4 spmm_row_h(const __half* __restrict__ T,
                                             int s, int e, int lane) {
    float4 a = make_float4(0.f, 0.f, 0.f, 0.f);
    const uint2* Tv = (const uint2*)T;    // 4 halves per uint2; row stride = 32
    int i = s;
    for (; i + 3 < e; i += 4) {
        int2 e0 = __ldg(&g_edges[i]);
        int2 e1 = __ldg(&g_edges[i + 1]);
        int2 e2 = __ldg(&g_edges[i + 2]);
        int2 e3 = __ldg(&g_edges[i + 3]);
        uint2 r0 = __ldg(&Tv[e0.x * 32 + lane]);
        uint2 r1 = __ldg(&Tv[e1.x * 32 + lane]);
        uint2 r2 = __ldg(&Tv[e2.x * 32 + lane]);
        uint2 r3 = __ldg(&Tv[e3.x * 32 + lane]);
        fma_h(a, r0, __int_as_float(e0.y));
        fma_h(a, r1, __int_as_float(e1.y));
        fma_h(a, r2, __int_as_float(e2.y));
        fma_h(a, r3, __int_as_float(e3.y));
    }
    for (; i < e; i++) {
        int2 e0 = __ldg(&g_edges[i]);
        uint2 r0 = __ldg(&Tv[e0.x * 32 + lane]);
        fma_h(a, r0, __int_as_float(e0.y));
    }
    return a;
}

// T1 = L @ T0 (slot0 -> slot1); one row per warp
__global__ void cheb_first(const __half* __restrict__ T0,
                           __half* __restrict__ T1) {
    int gw   = (blockIdx.x * blockDim.x + threadIdx.x) >> 5;
    int lane = threadIdx.x & 31;
    if (gw >= NN) return;
    int s = g_rptr[gw], e = g_rptr[gw + 1];

    float4 a = spmm_row_h(T0, s, e, lane);
    ((uint2*)T1)[gw * 32 + lane] = pack_h(a);
}

// Tk = 2*(L @ Tc) - Tp  (slot k-1, slot k-2 -> slot k); one row per warp
__global__ void cheb_step(const __half* __restrict__ Tc,
                          const __half* __restrict__ Tp,
                          __half* __restrict__ Tn) {
    int gw   = (blockIdx.x * blockDim.x + threadIdx.x) >> 5;
    int lane = threadIdx.x & 31;
    if (gw >= NN) return;
    int s = g_rptr[gw], e = g_rptr[gw + 1];

    float4 a = spmm_row_h(Tc, s, e, lane);

    int idx = gw * 32 + lane;
    uint2 tpr = __ldg(&((const uint2*)Tp)[idx]);
    float2 tplo = __half22float2(*(const __half2*)&tpr.x);
    float2 tphi = __half22float2(*(const __half2*)&tpr.y);

    float4 tk;
    tk.x = 2.f * a.x - tplo.x;
    tk.y = 2.f * a.y - tplo.y;
    tk.z = 2.f * a.z - tphi.x;
    tk.w = 2.f * a.w - tphi.y;
    ((uint2*)Tn)[idx] = pack_h(tk);
}

// out = sum_k coeffs[k] * T_k ; iterate k DESCENDING so the newest (L2-hot)
// slots are read before eviction.
__global__ void reduce_kernel(const __half* __restrict__ T,
                              const float* __restrict__ coeffs,
                              float* __restrict__ out, int M) {
    int i = blockIdx.x * blockDim.x + threadIdx.x;
    if (i >= NV2) return;
    const uint2* base = (const uint2*)T;
    float4 a = make_float4(0.f, 0.f, 0.f, 0.f);
    int k = M - 1;
    for (; k >= 3; k -= 4) {
        uint2 r0 = __ldg(&base[(size_t)(k - 0) * NV2 + i]);
        uint2 r1 = __ldg(&base[(size_t)(k - 1) * NV2 + i]);
        uint2 r2 = __ldg(&base[(size_t)(k - 2) * NV2 + i]);
        uint2 r3 = __ldg(&base[(size_t)(k - 3) * NV2 + i]);
        fma_h(a, r0, __ldg(&coeffs[k - 0]));
        fma_h(a, r1, __ldg(&coeffs[k - 1]));
        fma_h(a, r2, __ldg(&coeffs[k - 2]));
        fma_h(a, r3, __ldg(&coeffs[k - 3]));
    }
    for (; k >= 0; k--) {
        uint2 r = __ldg(&base[(size_t)k * NV2 + i]);
        fma_h(a, r, __ldg(&coeffs[k]));
    }
    ((float4*)out)[i] = a;
}

// ---------------- launch ----------------
extern "C" void kernel_launch(void* const* d_in, const int* in_sizes, int n_in,
                              void* d_out, int out_size) {
    const int*   rows   = (const int*)d_in[0];
    const int*   cols   = (const int*)d_in[1];
    const float* vals   = (const float*)d_in[2];
    const float* X      = (const float*)d_in[3];
    const float* coeffs = (const float*)d_in[4];
    const int nnz = in_sizes[0];
    const int M   = in_sizes[4];

    void* p;
    __half* T;
    int* pcnt;
    cudaGetSymbolAddress(&p, g_T);   T = (__half*)p;
    cudaGetSymbolAddress(&p, g_cnt); pcnt = (int*)p;

    const size_t SLOT = (size_t)NN * DD;

    // ---- CSR build (in-graph, re-done every replay) ----
    cudaMemsetAsync(pcnt, 0, NN * sizeof(int));
    hist_kernel<<<(nnz + 255) / 256, 256>>>(rows, nnz);
    scan_blocks_kernel<<<NBLK, SCAN_BLK>>>();
    scan_totals_kernel<<<1, SCAN_BLK>>>(nnz);
    scan_fixup_kernel<<<NBLK, SCAN_BLK>>>();
    scatter_kernel<<<(nnz + 255) / 256, 256>>>(rows, cols, vals, nnz);

    // ---- X -> fp16 slot 0 ----
    convert_kernel<<<(NV2 + 255) / 256, 256>>>(X, T);

    // ---- Chebyshev recurrence: slot k = T_k (one row per warp) ----
    const int threads = 256;                 // 8 rows per block
    const int rowsPerBlk = threads / 32;
    const int grid = (NN + rowsPerBlk - 1) / rowsPerBlk;

    cheb_first<<<grid, threads>>>(T, T + SLOT);
    for (int k = 2; k < M; k++) {
        cheb_step<<<grid, threads>>>(T + (size_t)(k - 1) * SLOT,
                                     T + (size_t)(k - 2) * SLOT,
                                     T + (size_t)k * SLOT);
    }

    // ---- final weighted reduction (descending k) ----
    reduce_kernel<<<(NV2 + 255) / 256, 256>>>(T, coeffs, (float*)d_out, M);
}